// round 1
// baseline (speedup 1.0000x reference)
#include <cuda_runtime.h>
#include <cstdint>

// ---------------- problem constants ----------------
#define NROW   512          // B*S = 8*64
#define LT     32
#define LC     128
#define LTOT   160          // LT + LC
#define D_EMB  150
#define H      64
#define G3     192          // 3*H
#define NT     6
#define NC     6

#define N_GEMM (NROW * LTOT)        // 81920 rows for all input GEMMs
#define ENC_OUT_ELEMS (NROW * LTOT * H)      // 3,276,800
#define HID_ELEMS     (8 * 4 * 64 * H)       // 131,072
#define HID_OFF  ENC_OUT_ELEMS
#define PRICE_OFF (ENC_OUT_ELEMS + HID_ELEMS)

// ---------------- scratch (device globals; no runtime alloc) ----------------
__device__ float g_e [NROW * LTOT * D_EMB];   // embedding sums, layer-0 input
__device__ float g_xg[NROW * LTOT * G3];      // precomputed input gates (current layer)
__device__ float g_ya[NROW * LTOT * H];       // ping
__device__ float g_yb[NROW * LTOT * H];       // pong
__device__ float g_wt[D_EMB * G3];            // transposed Wih for current layer

// ---------------- kernels ----------------

// One block per (row, t) output token; 160 threads over D; sum 6 gathers.
__global__ void embed_kernel(const int* __restrict__ titles,
                             const int* __restrict__ contents,
                             const float* __restrict__ emb,
                             float* __restrict__ E) {
    int n = blockIdx.x;              // 0 .. NROW*LTOT-1
    int d = threadIdx.x;
    if (d >= D_EMB) return;
    int rs = n / LTOT;
    int t  = n - rs * LTOT;
    float s = 0.f;
    if (t < LT) {
        const int* p = titles + rs * NT * LT + t;
        #pragma unroll
        for (int nn = 0; nn < NT; ++nn) {
            int ix = p[nn * LT];
            if (ix) s += emb[(size_t)ix * D_EMB + d];   // padding_idx=0 contributes 0
        }
    } else {
        const int* p = contents + rs * NC * LC + (t - LT);
        #pragma unroll
        for (int nn = 0; nn < NC; ++nn) {
            int ix = p[nn * LC];
            if (ix) s += emb[(size_t)ix * D_EMB + d];
        }
    }
    E[(size_t)n * D_EMB + d] = s;
}

// WT[k][g] = W[g][k]
__global__ void transpose_w(const float* __restrict__ W, float* __restrict__ WT, int K) {
    int i = blockIdx.x * 256 + threadIdx.x;
    if (i < K * G3) {
        int g = i / K, k = i - g * K;
        WT[k * G3 + g] = W[i];
    }
}

// XG[n, g] = bias[g] + sum_d X[n,d] * WT[d,g]
// Tile: 64 rows x 192 cols per block, 256 threads, thread -> 8 rows x 6 cols.
__global__ __launch_bounds__(256) void gemm_xg(const float* __restrict__ X,
                                               const float* __restrict__ WT,
                                               const float* __restrict__ bias,
                                               float* __restrict__ XG, int K) {
    __shared__ float Xs[64][33];
    __shared__ float Ws[32][193];
    int row0 = blockIdx.x * 64;
    int tid  = threadIdx.x;
    int wy   = tid >> 5;       // 0..7  (uniform within warp)
    int wx   = tid & 31;       // lane
    float acc[8][6];
    #pragma unroll
    for (int r = 0; r < 8; ++r)
        #pragma unroll
        for (int c = 0; c < 6; ++c) acc[r][c] = 0.f;

    for (int k0 = 0; k0 < K; k0 += 32) {
        int kk = K - k0; if (kk > 32) kk = 32;
        for (int i = tid; i < 64 * 32; i += 256) {
            int r = i >> 5, k = i & 31;
            Xs[r][k] = (k < kk) ? X[(size_t)(row0 + r) * K + k0 + k] : 0.f;
        }
        for (int i = tid; i < 32 * G3; i += 256) {
            int k = i / G3, g = i - k * G3;
            Ws[k][g] = (k < kk) ? WT[(k0 + k) * G3 + g] : 0.f;
        }
        __syncthreads();
        #pragma unroll
        for (int k = 0; k < 32; ++k) {
            float xv[8], wv[6];
            #pragma unroll
            for (int r = 0; r < 8; ++r) xv[r] = Xs[wy * 8 + r][k];
            #pragma unroll
            for (int c = 0; c < 6; ++c) wv[c] = Ws[k][wx * 6 + c];
            #pragma unroll
            for (int r = 0; r < 8; ++r)
                #pragma unroll
                for (int c = 0; c < 6; ++c) acc[r][c] += xv[r] * wv[c];
        }
        __syncthreads();
    }
    #pragma unroll
    for (int c = 0; c < 6; ++c) {
        float b = bias[wx * 6 + c];
        #pragma unroll
        for (int r = 0; r < 8; ++r)
            XG[(size_t)(row0 + wy * 8 + r) * G3 + wx * 6 + c] = acc[r][c] + b;
    }
}

__device__ __forceinline__ float sigf(float x) { return 1.f / (1.f + expf(-x)); }

// GRU recurrence for one layer. One block per batch row, 192 threads (one per gate).
// Thread g keeps Whh row g in registers; h broadcast from smem.
// reset_t: zero h at that timestep (info GRU: titles|contents boundary). -1 = none.
// hid != nullptr: write last hidden into [b, layer, s, :] of hidden output region.
__global__ __launch_bounds__(192) void gru_rec(const float* __restrict__ xg,
                                               const float* __restrict__ Whh,
                                               const float* __restrict__ bhh,
                                               float* __restrict__ y,
                                               float* __restrict__ hid,
                                               int layer, int reset_t) {
    __shared__ __align__(16) float hs[H];
    __shared__ float rs_s[H];
    __shared__ float ns_s[H];
    int row = blockIdx.x;
    int g   = threadIdx.x;               // 0..191

    float w[H];
    #pragma unroll
    for (int k = 0; k < H; ++k) w[k] = Whh[g * H + k];
    float bg = bhh[g];

    const float* xr = xg + (size_t)row * LTOT * G3 + g;
    float*       yr = y  + (size_t)row * LTOT * H;

    if (g < H) hs[g] = 0.f;
    __syncthreads();

    float xv = xr[0];
    for (int t = 0; t < LTOT; ++t) {
        float xnext = (t < LTOT - 1) ? xr[(size_t)(t + 1) * G3] : 0.f;  // prefetch
        if (t == reset_t) {
            if (g < H) hs[g] = 0.f;
            __syncthreads();
        }
        float acc = bg;
        #pragma unroll
        for (int k = 0; k < H; k += 4) {
            float4 h4 = *(const float4*)&hs[k];
            acc += w[k] * h4.x + w[k + 1] * h4.y + w[k + 2] * h4.z + w[k + 3] * h4.w;
        }
        if (g < H) {                               // r gate
            rs_s[g] = sigf(xv + acc);
        }
        __syncthreads();
        if (g >= 2 * H) {                          // n gate: tanh(xn + r*ghn)
            int i = g - 2 * H;
            ns_s[i] = tanhf(xv + rs_s[i] * acc);
        }
        __syncthreads();
        if (g >= H && g < 2 * H) {                 // z gate + state update
            int i = g - H;
            float z = sigf(xv + acc);
            float hnew = (1.f - z) * ns_s[i] + z * hs[i];
            hs[i] = hnew;
            yr[(size_t)t * H + i] = hnew;
            if (hid != nullptr && t == LTOT - 1) {
                int b = row >> 6, s = row & 63;    // row = b*64+s
                hid[(((size_t)b * 4 + layer) * 64 + s) * H + i] = hnew;
            }
        }
        __syncthreads();
        xv = xnext;
    }
}

__global__ void tail_kernel(const float* __restrict__ prices, float* __restrict__ out) {
    int i = blockIdx.x * 256 + threadIdx.x;
    if (i < NROW) out[PRICE_OFF + i] = prices[i];
}

// ---------------- host launcher ----------------
extern "C" void kernel_launch(void* const* d_in, const int* in_sizes, int n_in,
                              void* d_out, int out_size) {
    const int*   titles    = (const int*)  d_in[0];
    const int*   contents  = (const int*)  d_in[1];
    const float* prices    = (const float*)d_in[2];
    const float* emb       = (const float*)d_in[3];
    const float* iWih0     = (const float*)d_in[4];   // [192,150]
    const float* iWhh0     = (const float*)d_in[5];   // [192,64]
    const float* ibih0     = (const float*)d_in[6];
    const float* ibhh0     = (const float*)d_in[7];
    const float* iWih      = (const float*)d_in[8];   // [3,192,64]
    const float* iWhh      = (const float*)d_in[9];
    const float* ibih      = (const float*)d_in[10];  // [3,192]
    const float* ibhh      = (const float*)d_in[11];
    const float* cWih      = (const float*)d_in[12];  // [4,192,64]
    const float* cWhh      = (const float*)d_in[13];
    const float* cbih      = (const float*)d_in[14];  // [4,192]
    const float* cbhh      = (const float*)d_in[15];
    float* out = (float*)d_out;

    float *e, *xg, *ya, *yb, *wt;
    cudaGetSymbolAddress((void**)&e,  g_e);
    cudaGetSymbolAddress((void**)&xg, g_xg);
    cudaGetSymbolAddress((void**)&ya, g_ya);
    cudaGetSymbolAddress((void**)&yb, g_yb);
    cudaGetSymbolAddress((void**)&wt, g_wt);

    // 1) embedding-bag sums -> E [512,160,150]
    embed_kernel<<<NROW * LTOT, 160>>>(titles, contents, emb, e);

    const int nGemmBlocks = N_GEMM / 64;   // 1280

    float* bufs[2] = { ya, yb };
    const float* cur = e;   // layer input
    int pp = 0;

    // 2) info GRU, 4 layers, h reset at t=32
    for (int l = 0; l < 4; ++l) {
        const float* Wih = (l == 0) ? iWih0 : iWih + (size_t)(l - 1) * G3 * H;
        const float* Whh = (l == 0) ? iWhh0 : iWhh + (size_t)(l - 1) * G3 * H;
        const float* bih = (l == 0) ? ibih0 : ibih + (size_t)(l - 1) * G3;
        const float* bhh = (l == 0) ? ibhh0 : ibhh + (size_t)(l - 1) * G3;
        int K = (l == 0) ? D_EMB : H;
        transpose_w<<<(K * G3 + 255) / 256, 256>>>(Wih, wt, K);
        gemm_xg<<<nGemmBlocks, 256>>>(cur, wt, bih, xg, K);
        float* yo = bufs[pp];
        gru_rec<<<NROW, G3>>>(xg, Whh, bhh, yo, nullptr, l, LT);
        cur = yo; pp ^= 1;
    }

    // 3) comb GRU, 4 layers, no reset; last layer writes encoder_outputs directly,
    //    every layer records last hidden into the hidden region of d_out.
    for (int l = 0; l < 4; ++l) {
        const float* Wih = cWih + (size_t)l * G3 * H;
        const float* Whh = cWhh + (size_t)l * G3 * H;
        const float* bih = cbih + (size_t)l * G3;
        const float* bhh = cbhh + (size_t)l * G3;
        transpose_w<<<(H * G3 + 255) / 256, 256>>>(Wih, wt, H);
        gemm_xg<<<nGemmBlocks, 256>>>(cur, wt, bih, xg, H);
        float* yo = (l == 3) ? out : bufs[pp];
        gru_rec<<<NROW, G3>>>(xg, Whh, bhh, yo, out + HID_OFF, l, -1);
        cur = yo; pp ^= 1;
    }

    // 4) prices passthrough
    tail_kernel<<<(NROW + 255) / 256, 256>>>(prices, out);
}

// round 2
// speedup vs baseline: 1.1887x; 1.1887x over previous
#include <cuda_runtime.h>
#include <cstdint>

// ---------------- problem constants ----------------
#define NROW   512          // B*S = 8*64
#define LT     32
#define LC     128
#define LTOT   160          // LT + LC
#define D_EMB  150
#define H      64
#define G3     192          // 3*H
#define NT     6
#define NC     6

#define N_GEMM (NROW * LTOT)        // 81920 rows for all input GEMMs
#define ENC_OUT_ELEMS (NROW * LTOT * H)      // 3,276,800
#define HID_ELEMS     (8 * 4 * 64 * H)       // 131,072
#define HID_OFF  ENC_OUT_ELEMS
#define PRICE_OFF (ENC_OUT_ELEMS + HID_ELEMS)

// ---------------- scratch (device globals; no runtime alloc) ----------------
__device__ float g_e [NROW * LTOT * D_EMB];   // embedding sums, layer-0 input
__device__ float g_xg[NROW * LTOT * G3];      // precomputed input gates (current layer)
__device__ float g_ya[NROW * LTOT * H];       // ping
__device__ float g_yb[NROW * LTOT * H];       // pong
__device__ float g_wt[D_EMB * G3];            // transposed Wih for current layer

// ---------------- kernels ----------------

// One block per (row, t) output token; 160 threads over D; sum 6 gathers.
__global__ void embed_kernel(const int* __restrict__ titles,
                             const int* __restrict__ contents,
                             const float* __restrict__ emb,
                             float* __restrict__ E) {
    int n = blockIdx.x;              // 0 .. NROW*LTOT-1
    int d = threadIdx.x;
    if (d >= D_EMB) return;
    int rs = n / LTOT;
    int t  = n - rs * LTOT;
    float s = 0.f;
    if (t < LT) {
        const int* p = titles + rs * NT * LT + t;
        #pragma unroll
        for (int nn = 0; nn < NT; ++nn) {
            int ix = p[nn * LT];
            if (ix) s += emb[(size_t)ix * D_EMB + d];   // padding_idx=0 contributes 0
        }
    } else {
        const int* p = contents + rs * NC * LC + (t - LT);
        #pragma unroll
        for (int nn = 0; nn < NC; ++nn) {
            int ix = p[nn * LC];
            if (ix) s += emb[(size_t)ix * D_EMB + d];
        }
    }
    E[(size_t)n * D_EMB + d] = s;
}

// WT[k][g] = W[g][k]
__global__ void transpose_w(const float* __restrict__ W, float* __restrict__ WT, int K) {
    int i = blockIdx.x * 256 + threadIdx.x;
    if (i < K * G3) {
        int g = i / K, k = i - g * K;
        WT[k * G3 + g] = W[i];
    }
}

// XG[n, g] = bias[g] + sum_d X[n,d] * WT[d,g]
// Tile: 64 rows x 192 cols per block, 256 threads, thread -> 8 rows x 6 cols.
__global__ __launch_bounds__(256) void gemm_xg(const float* __restrict__ X,
                                               const float* __restrict__ WT,
                                               const float* __restrict__ bias,
                                               float* __restrict__ XG, int K) {
    __shared__ float Xs[64][33];
    __shared__ float Ws[32][193];
    int row0 = blockIdx.x * 64;
    int tid  = threadIdx.x;
    int wy   = tid >> 5;       // 0..7  (uniform within warp)
    int wx   = tid & 31;       // lane
    float acc[8][6];
    #pragma unroll
    for (int r = 0; r < 8; ++r)
        #pragma unroll
        for (int c = 0; c < 6; ++c) acc[r][c] = 0.f;

    for (int k0 = 0; k0 < K; k0 += 32) {
        int kk = K - k0; if (kk > 32) kk = 32;
        for (int i = tid; i < 64 * 32; i += 256) {
            int r = i >> 5, k = i & 31;
            Xs[r][k] = (k < kk) ? X[(size_t)(row0 + r) * K + k0 + k] : 0.f;
        }
        for (int i = tid; i < 32 * G3; i += 256) {
            int k = i / G3, g = i - k * G3;
            Ws[k][g] = (k < kk) ? WT[(k0 + k) * G3 + g] : 0.f;
        }
        __syncthreads();
        #pragma unroll
        for (int k = 0; k < 32; ++k) {
            float xv[8], wv[6];
            #pragma unroll
            for (int r = 0; r < 8; ++r) xv[r] = Xs[wy * 8 + r][k];
            #pragma unroll
            for (int c = 0; c < 6; ++c) wv[c] = Ws[k][wx * 6 + c];
            #pragma unroll
            for (int r = 0; r < 8; ++r)
                #pragma unroll
                for (int c = 0; c < 6; ++c) acc[r][c] += xv[r] * wv[c];
        }
        __syncthreads();
    }
    #pragma unroll
    for (int c = 0; c < 6; ++c) {
        float b = bias[wx * 6 + c];
        #pragma unroll
        for (int r = 0; r < 8; ++r)
            XG[(size_t)(row0 + wy * 8 + r) * G3 + wx * 6 + c] = acc[r][c] + b;
    }
}

// ---- fast activations: single-MUFU tanh.approx (sm_75+) ----
__device__ __forceinline__ float fast_tanh(float x) {
    float y;
    asm("tanh.approx.f32 %0, %1;" : "=f"(y) : "f"(x));
    return y;
}
__device__ __forceinline__ float fast_sig(float x) {
    return fmaf(0.5f, fast_tanh(0.5f * x), 0.5f);
}

// GRU recurrence for one layer. One block per batch row, 192 threads (one per gate-row).
// Thread g keeps Whh row g entirely in registers; h broadcast from smem.
// Per step: all threads produce their hh-preactivation into smem (1 phase),
// then threads 0..63 do r,z,n + state update together (1 phase). 2 barriers/step.
// reset_t: zero h at that timestep (info GRU: titles|contents boundary). -1 = none.
__global__ __launch_bounds__(192) void gru_rec(const float* __restrict__ xg,
                                               const float* __restrict__ Whh,
                                               const float* __restrict__ bhh,
                                               float* __restrict__ y,
                                               float* __restrict__ hid,
                                               int layer, int reset_t) {
    __shared__ __align__(16) float hs[H];
    __shared__ float acc_s[G3];   // hh-preactivation per gate-row
    __shared__ float xs[G3];      // input-gate value per gate-row
    int row = blockIdx.x;
    int g   = threadIdx.x;               // 0..191

    float w[H];
    #pragma unroll
    for (int k = 0; k < H; ++k) w[k] = Whh[g * H + k];
    float bg = bhh[g];

    const float* xr = xg + (size_t)row * LTOT * G3 + g;
    float*       yr = y  + (size_t)row * LTOT * H;

    if (g < H) hs[g] = 0.f;
    __syncthreads();

    float xv = xr[0];
    for (int t = 0; t < LTOT; ++t) {
        float xnext = (t < LTOT - 1) ? xr[(size_t)(t + 1) * G3] : 0.f;  // prefetch
        if (t == reset_t) {
            if (g < H) hs[g] = 0.f;
            __syncthreads();
        }
        // hh matvec: 4 independent accumulator chains
        float a0 = 0.f, a1 = 0.f, a2 = 0.f, a3 = 0.f;
        #pragma unroll
        for (int k = 0; k < H; k += 16) {
            float4 p0 = *(const float4*)&hs[k];
            float4 p1 = *(const float4*)&hs[k + 4];
            float4 p2 = *(const float4*)&hs[k + 8];
            float4 p3 = *(const float4*)&hs[k + 12];
            a0 = fmaf(w[k+0], p0.x, a0); a0 = fmaf(w[k+1], p0.y, a0);
            a0 = fmaf(w[k+2], p0.z, a0); a0 = fmaf(w[k+3], p0.w, a0);
            a1 = fmaf(w[k+4], p1.x, a1); a1 = fmaf(w[k+5], p1.y, a1);
            a1 = fmaf(w[k+6], p1.z, a1); a1 = fmaf(w[k+7], p1.w, a1);
            a2 = fmaf(w[k+8],  p2.x, a2); a2 = fmaf(w[k+9],  p2.y, a2);
            a2 = fmaf(w[k+10], p2.z, a2); a2 = fmaf(w[k+11], p2.w, a2);
            a3 = fmaf(w[k+12], p3.x, a3); a3 = fmaf(w[k+13], p3.y, a3);
            a3 = fmaf(w[k+14], p3.z, a3); a3 = fmaf(w[k+15], p3.w, a3);
        }
        acc_s[g] = bg + (a0 + a1) + (a2 + a3);
        xs[g]    = xv;
        __syncthreads();

        if (g < H) {
            float hr = acc_s[g];
            float hz = acc_s[g + H];
            float hn = acc_s[g + 2 * H];
            float r  = fast_sig(xs[g] + hr);
            float z  = fast_sig(xs[g + H] + hz);
            float n  = fast_tanh(fmaf(r, hn, xs[g + 2 * H]));
            float hold = hs[g];
            float hnew = fmaf(z, hold - n, n);    // (1-z)*n + z*h
            hs[g] = hnew;
            yr[(size_t)t * H + g] = hnew;
            if (hid != nullptr && t == LTOT - 1) {
                int b = row >> 6, s = row & 63;   // row = b*64 + s
                hid[(((size_t)b * 4 + layer) * 64 + s) * H + g] = hnew;
            }
        }
        __syncthreads();
        xv = xnext;
    }
}

__global__ void tail_kernel(const float* __restrict__ prices, float* __restrict__ out) {
    int i = blockIdx.x * 256 + threadIdx.x;
    if (i < NROW) out[PRICE_OFF + i] = prices[i];
}

// ---------------- host launcher ----------------
extern "C" void kernel_launch(void* const* d_in, const int* in_sizes, int n_in,
                              void* d_out, int out_size) {
    const int*   titles    = (const int*)  d_in[0];
    const int*   contents  = (const int*)  d_in[1];
    const float* prices    = (const float*)d_in[2];
    const float* emb       = (const float*)d_in[3];
    const float* iWih0     = (const float*)d_in[4];   // [192,150]
    const float* iWhh0     = (const float*)d_in[5];   // [192,64]
    const float* ibih0     = (const float*)d_in[6];
    const float* ibhh0     = (const float*)d_in[7];
    const float* iWih      = (const float*)d_in[8];   // [3,192,64]
    const float* iWhh      = (const float*)d_in[9];
    const float* ibih      = (const float*)d_in[10];  // [3,192]
    const float* ibhh      = (const float*)d_in[11];
    const float* cWih      = (const float*)d_in[12];  // [4,192,64]
    const float* cWhh      = (const float*)d_in[13];
    const float* cbih      = (const float*)d_in[14];  // [4,192]
    const float* cbhh      = (const float*)d_in[15];
    float* out = (float*)d_out;

    float *e, *xg, *ya, *yb, *wt;
    cudaGetSymbolAddress((void**)&e,  g_e);
    cudaGetSymbolAddress((void**)&xg, g_xg);
    cudaGetSymbolAddress((void**)&ya, g_ya);
    cudaGetSymbolAddress((void**)&yb, g_yb);
    cudaGetSymbolAddress((void**)&wt, g_wt);

    // 1) embedding-bag sums -> E [512,160,150]
    embed_kernel<<<NROW * LTOT, 160>>>(titles, contents, emb, e);

    const int nGemmBlocks = N_GEMM / 64;   // 1280

    float* bufs[2] = { ya, yb };
    const float* cur = e;   // layer input
    int pp = 0;

    // 2) info GRU, 4 layers, h reset at t=32
    for (int l = 0; l < 4; ++l) {
        const float* Wih = (l == 0) ? iWih0 : iWih + (size_t)(l - 1) * G3 * H;
        const float* Whh = (l == 0) ? iWhh0 : iWhh + (size_t)(l - 1) * G3 * H;
        const float* bih = (l == 0) ? ibih0 : ibih + (size_t)(l - 1) * G3;
        const float* bhh = (l == 0) ? ibhh0 : ibhh + (size_t)(l - 1) * G3;
        int K = (l == 0) ? D_EMB : H;
        transpose_w<<<(K * G3 + 255) / 256, 256>>>(Wih, wt, K);
        gemm_xg<<<nGemmBlocks, 256>>>(cur, wt, bih, xg, K);
        float* yo = bufs[pp];
        gru_rec<<<NROW, G3>>>(xg, Whh, bhh, yo, nullptr, l, LT);
        cur = yo; pp ^= 1;
    }

    // 3) comb GRU, 4 layers, no reset; last layer writes encoder_outputs directly,
    //    every layer records last hidden into the hidden region of d_out.
    for (int l = 0; l < 4; ++l) {
        const float* Wih = cWih + (size_t)l * G3 * H;
        const float* Whh = cWhh + (size_t)l * G3 * H;
        const float* bih = cbih + (size_t)l * G3;
        const float* bhh = cbhh + (size_t)l * G3;
        transpose_w<<<(H * G3 + 255) / 256, 256>>>(Wih, wt, H);
        gemm_xg<<<nGemmBlocks, 256>>>(cur, wt, bih, xg, H);
        float* yo = (l == 3) ? out : bufs[pp];
        gru_rec<<<NROW, G3>>>(xg, Whh, bhh, yo, out + HID_OFF, l, -1);
        cur = yo; pp ^= 1;
    }

    // 4) prices passthrough
    tail_kernel<<<(NROW + 255) / 256, 256>>>(prices, out);
}